// round 4
// baseline (speedup 1.0000x reference)
#include <cuda_runtime.h>

// Input order (reference signature):
// 0 features(256,50,51,2) 1 W1(4,64,2) 2 a1(4,128) 3 W2(128,256) 4 a2(256)
// 5 Wih0(128,51) 6 Whh0(128,32) 7 bih0(128) 8 bhh0(128)
// 9 Wih1(128,32) 10 Whh1(128,32) 11 bih1(128) 12 bhh1(128)
// 13 Wfc(8,1600) 14 bfc(8)   -> out float32 (256,8)

#define DINL __device__ __forceinline__

constexpr int NN = 51;
constexpr int G  = 12800;   // B*F
constexpr int BB = 256;
constexpr int FF = 50;

// ---------------- device scratch (no allocations allowed) ----------------
__device__ float g_X0g[G * 128];         // packed [g][j][q] layer-0 input gates
__device__ float g_Y[BB * FF * 32];      // lstm layer-2 hidden states
__device__ float g_v1[256], g_v2[256], g_v3[256];
__device__ float g_ps[8], g_pd[8];
__device__ float g_b0p[128], g_b1p[128];
__device__ float g_WhhP0[32 * 128], g_WihP1[32 * 128], g_WhhP1[32 * 128];
__device__ float g_Wih0P[NN * 128];

// ---------------- prep: fold constants, pack weights ----------------
__global__ void prep_kernel(const float* __restrict__ W1, const float* __restrict__ a1,
                            const float* __restrict__ W2, const float* __restrict__ a2,
                            const float* __restrict__ Wih0, const float* __restrict__ Whh0,
                            const float* __restrict__ bih0, const float* __restrict__ bhh0,
                            const float* __restrict__ Wih1, const float* __restrict__ Whh1,
                            const float* __restrict__ bih1, const float* __restrict__ bhh1) {
    int t = threadIdx.x;  // 256 threads
    if (t < 8) {
        int h = t >> 1, c = t & 1;
        float s = 0.f, d = 0.f;
        for (int o = 0; o < 64; o++) {
            float w = W1[(h * 64 + o) * 2 + c];
            s += w * a1[h * 128 + o];
            d += w * a1[h * 128 + 64 + o];
        }
        g_ps[t] = s; g_pd[t] = d;
    }
    {   // v1 = W2^T a2_src, v2 = W2^T a2_dst, v3 = W2 column-mean
        float s1 = 0.f, s2 = 0.f, s3 = 0.f;
        for (int o = 0; o < 128; o++) {
            float w = W2[o * 256 + t];
            s1 += w * a2[o];
            s2 += w * a2[128 + o];
            s3 += w;
        }
        g_v1[t] = s1; g_v2[t] = s2; g_v3[t] = s3 * (1.f / 128.f);
    }
    if (t < 128) {
        int j = t >> 2, q = t & 3, k = q * 32 + j;
        g_b0p[t] = bih0[k] + bhh0[k];
        g_b1p[t] = bih1[k] + bhh1[k];
    }
    for (int idx = t; idx < 32 * 128; idx += 256) {
        int m = idx >> 7, r = idx & 127;
        int j = r >> 2, q = r & 3, k = q * 32 + j;
        g_WhhP0[idx] = Whh0[k * 32 + m];
        g_WihP1[idx] = Wih1[k * 32 + m];
        g_WhhP1[idx] = Whh1[k * 32 + m];
    }
    for (int idx = t; idx < NN * 128; idx += 256) {
        int n = idx >> 7, r = idx & 127;
        int j = r >> 2, q = r & 3, k = q * 32 + j;
        g_Wih0P[idx] = Wih0[k * NN + n];
    }
}

// ---------------- fused 2-layer GAT + lstm-layer-0 input transform ----------------
// One CTA per graph, 256 threads, ~3KB smem.
// Rank-2 collapse: Z1[i,d] = x0_i*wx_d + x1_i*wy_d, so
//   h1[j,h,d] = S0[h,j]*wx[h,d] + S1[h,j]*wy[h,d],
//   S0/S1 = attention-weighted sums of the two input features.
// The alpha @ Z1 GEMM is never formed; attention weights are never stored.
__global__ void __launch_bounds__(256)
gat_kernel(const float* __restrict__ feat, const float* __restrict__ W1) {
    __shared__ float xs[NN * 2];
    __shared__ float esm[4 * NN], edm[4 * NN];       // [h*51+n]
    __shared__ float S0n[4 * NN], S1n[4 * NN];       // normalized attn-weighted feats
    __shared__ float wxs[256], wys[256];
    __shared__ float v1s[256], v2s[256], v3s[256];
    __shared__ float wred[NN * 4 * 3];               // [(j*4+q)*3]
    __shared__ float es2[NN], ed2[NN], zb[NN], exv[NN];

    int g = blockIdx.x;
    int t = threadIdx.x;

    // stage folded weights (L1-hot after first wave)
    {
        float2 w = ((const float2*)W1)[t];           // W1[d][0..1]
        wxs[t] = w.x; wys[t] = w.y;
        v1s[t] = g_v1[t]; v2s[t] = g_v2[t]; v3s[t] = g_v3[t];
    }
    if (t < NN * 2) xs[t] = feat[g * NN * 2 + t];
    __syncthreads();

    // es/ed per (h, n)
    if (t < 4 * NN) {
        int h = t / NN, n = t % NN;
        float x0 = xs[2 * n], x1 = xs[2 * n + 1];
        esm[t] = x0 * g_ps[h * 2] + x1 * g_ps[h * 2 + 1];
        edm[t] = x0 * g_pd[h * 2] + x1 * g_pd[h * 2 + 1];
    }
    __syncthreads();

    // fused softmax + attention-weighted feature sums.
    // Single-pass exp (logits bounded, softmax shift-invariant; diag -> 0).
    if (t < 4 * NN) {
        int j = t % NN;                              // t = h*51 + j
        float ed = edm[t];
        const float* es = &esm[t - j];               // row base h*51
        float S0 = 0.f, S1 = 0.f, s = 0.f;
        for (int i = 0; i < NN; i++) {
            float e = es[i] + ed;
            e = (e >= 0.f) ? e : 0.01f * e;
            float w = (i == j) ? 0.f : __expf(e);
            s  += w;
            S0 += w * xs[2 * i];
            S1 += w * xs[2 * i + 1];
        }
        float si = 1.f / s;
        S0n[t] = S0 * si;
        S1n[t] = S1 * si;
    }
    __syncthreads();

    // reconstruct h1 elementwise, elu, project onto v1/v2/v3.
    // thread (q, j): q = head = d-quarter, so S0n/S1n are loop-invariant.
    if (t < 4 * NN) {
        int q = t / NN, j = t % NN;
        float S0 = S0n[q * NN + j], S1 = S1n[q * NN + j];
        float s1 = 0.f, s2 = 0.f, s3 = 0.f;
        int dbase = q * 64;
        #pragma unroll 8
        for (int dd = 0; dd < 64; dd++) {
            int d = dbase + dd;
            float hv = S0 * wxs[d] + S1 * wys[d];
            hv = (hv > 0.f) ? hv : (__expf(hv) - 1.f);   // elu
            s1 += hv * v1s[d];
            s2 += hv * v2s[d];
            s3 += hv * v3s[d];
        }
        float* wr = &wred[(j * 4 + q) * 3];
        wr[0] = s1; wr[1] = s2; wr[2] = s3;
    }
    __syncthreads();
    if (t < NN) {
        const float* wr = &wred[t * 4 * 3];
        es2[t] = wr[0] + wr[3] + wr[6] + wr[9];
        ed2[t] = wr[1] + wr[4] + wr[7] + wr[10];
        zb[t]  = wr[2] + wr[5] + wr[8] + wr[11];
    }
    __syncthreads();

    // layer-2 attention + mean fused: extracted[j] = sum_i alpha2[i,j]*zb[i]
    if (t < NN) {
        int j = t;
        float ed = ed2[j];
        float num = 0.f, den = 0.f;
        for (int i = 0; i < NN; i++) {
            float e = es2[i] + ed;
            e = (e >= 0.f) ? e : 0.01f * e;
            float w = (i == j) ? 0.f : __expf(e);
            num += w * zb[i];
            den += w;
        }
        exv[j] = num / den;
    }
    __syncthreads();

    // fused lstm-layer-0 input gate transform: g_X0g[g][j][q] = b + ex . Wih0
    if (t < 128) {
        float acc0 = g_b0p[t];
        #pragma unroll 3
        for (int n = 0; n < NN; n++) acc0 += exv[n] * g_Wih0P[n * 128 + t];
        g_X0g[g * 128 + t] = acc0;
    }
}

DINL float sigf(float x)    { return __fdividef(1.f, 1.f + __expf(-x)); }
DINL float tanhfast(float x){ return 1.f - __fdividef(2.f, __expf(2.f * x) + 1.f); }

// ---------------- 2-layer LSTM recurrence: one warp per batch element ----------------
__global__ void __launch_bounds__(128)
lstm_kernel() {
    __shared__ float4 sW0[32 * 32], sW1[32 * 32], sW2[32 * 32];  // 48KB
    int tid = threadIdx.x;
    for (int idx = tid; idx < 32 * 32; idx += 128) {
        sW0[idx] = ((const float4*)g_WhhP0)[idx];
        sW1[idx] = ((const float4*)g_WihP1)[idx];
        sW2[idx] = ((const float4*)g_WhhP1)[idx];
    }
    __syncthreads();
    int w = blockIdx.x * 4 + (tid >> 5);  // global warp = batch index f
    if (w >= FF) return;
    int lane = tid & 31;
    float4 b1 = ((const float4*)g_b1p)[lane];
    float h0 = 0.f, c0 = 0.f, h1 = 0.f, c1 = 0.f;
    for (int tt = 0; tt < BB; tt++) {
        float4 xg = ((const float4*)g_X0g)[(tt * FF + w) * 32 + lane];
        float a0 = xg.x, a1 = xg.y, a2 = xg.z, a3 = xg.w;
        #pragma unroll
        for (int m = 0; m < 32; m++) {
            float hm = __shfl_sync(0xffffffffu, h0, m);
            float4 wv = sW0[m * 32 + lane];
            a0 += hm * wv.x; a1 += hm * wv.y; a2 += hm * wv.z; a3 += hm * wv.w;
        }
        float gi = sigf(a0), gf = sigf(a1), gg = tanhfast(a2), go = sigf(a3);
        c0 = gf * c0 + gi * gg;
        h0 = go * tanhfast(c0);

        a0 = b1.x; a1 = b1.y; a2 = b1.z; a3 = b1.w;
        #pragma unroll
        for (int m = 0; m < 32; m++) {
            float hm = __shfl_sync(0xffffffffu, h0, m);
            float4 wv = sW1[m * 32 + lane];
            a0 += hm * wv.x; a1 += hm * wv.y; a2 += hm * wv.z; a3 += hm * wv.w;
        }
        #pragma unroll
        for (int m = 0; m < 32; m++) {
            float hm = __shfl_sync(0xffffffffu, h1, m);
            float4 wv = sW2[m * 32 + lane];
            a0 += hm * wv.x; a1 += hm * wv.y; a2 += hm * wv.z; a3 += hm * wv.w;
        }
        gi = sigf(a0); gf = sigf(a1); gg = tanhfast(a2); go = sigf(a3);
        c1 = gf * c1 + gi * gg;
        h1 = go * tanhfast(c1);
        g_Y[(tt * FF + w) * 32 + lane] = h1;
    }
}

// ---------------- final FC ----------------
__global__ void fc_kernel(const float* __restrict__ Wfc, const float* __restrict__ bfc,
                          float* __restrict__ out) {
    int t = blockIdx.x;                 // time step (output row)
    int cls = threadIdx.x >> 5, lane = threadIdx.x & 31;
    const float* y  = &g_Y[t * 1600];
    const float* wr = &Wfc[cls * 1600];
    float acc = 0.f;
    for (int k = lane; k < 1600; k += 32) acc += y[k] * wr[k];
    #pragma unroll
    for (int off = 16; off; off >>= 1) acc += __shfl_xor_sync(0xffffffffu, acc, off);
    if (lane == 0) out[t * 8 + cls] = acc + bfc[cls];
}

extern "C" void kernel_launch(void* const* d_in, const int* in_sizes, int n_in,
                              void* d_out, int out_size) {
    const float* feat = (const float*)d_in[0];
    const float* W1   = (const float*)d_in[1];
    const float* a1   = (const float*)d_in[2];
    const float* W2   = (const float*)d_in[3];
    const float* a2   = (const float*)d_in[4];
    const float* Wih0 = (const float*)d_in[5];
    const float* Whh0 = (const float*)d_in[6];
    const float* bih0 = (const float*)d_in[7];
    const float* bhh0 = (const float*)d_in[8];
    const float* Wih1 = (const float*)d_in[9];
    const float* Whh1 = (const float*)d_in[10];
    const float* bih1 = (const float*)d_in[11];
    const float* bhh1 = (const float*)d_in[12];
    const float* Wfc  = (const float*)d_in[13];
    const float* bfc  = (const float*)d_in[14];
    float* out = (float*)d_out;

    prep_kernel<<<1, 256>>>(W1, a1, W2, a2, Wih0, Whh0, bih0, bhh0,
                            Wih1, Whh1, bih1, bhh1);
    gat_kernel<<<G, 256>>>(feat, W1);
    lstm_kernel<<<13, 128>>>();
    fc_kernel<<<BB, 256>>>(Wfc, bfc, out);
}

// round 10
// speedup vs baseline: 1.1047x; 1.1047x over previous
#include <cuda_runtime.h>
#include <cstdint>

// Input order (reference signature):
// 0 features(256,50,51,2) 1 W1(4,64,2) 2 a1(4,128) 3 W2(128,256) 4 a2(256)
// 5 Wih0(128,51) 6 Whh0(128,32) 7 bih0(128) 8 bhh0(128)
// 9 Wih1(128,32) 10 Whh1(128,32) 11 bih1(128) 12 bhh1(128)
// 13 Wfc(8,1600) 14 bfc(8)   -> out float32 (256,8)

#define DINL __device__ __forceinline__

constexpr int NN = 51;
constexpr int G  = 12800;   // B*F
constexpr int BB = 256;
constexpr int FF = 50;

// ---------------- device scratch (no allocations allowed) ----------------
__device__ float g_X0g[G * 128];         // packed [g][j][q] layer-0 input gates
__device__ float g_Y[BB * FF * 32];      // lstm layer-2 hidden states
__device__ float g_v1[256], g_v2[256], g_v3[256];
__device__ float g_ps[8], g_pd[8];
__device__ float g_b0p[128], g_b1p[128];
__device__ float g_WhhP0[32 * 128], g_WihP1[32 * 128], g_WhhP1[32 * 128];
__device__ float g_Wih0P[NN * 128];

// ---------------- prep: fold constants, pack weights ----------------
__global__ void prep_kernel(const float* __restrict__ W1, const float* __restrict__ a1,
                            const float* __restrict__ W2, const float* __restrict__ a2,
                            const float* __restrict__ Wih0, const float* __restrict__ Whh0,
                            const float* __restrict__ bih0, const float* __restrict__ bhh0,
                            const float* __restrict__ Wih1, const float* __restrict__ Whh1,
                            const float* __restrict__ bih1, const float* __restrict__ bhh1) {
    int t = threadIdx.x;  // 256 threads
    if (t < 8) {
        int h = t >> 1, c = t & 1;
        float s = 0.f, d = 0.f;
        for (int o = 0; o < 64; o++) {
            float w = W1[(h * 64 + o) * 2 + c];
            s += w * a1[h * 128 + o];
            d += w * a1[h * 128 + 64 + o];
        }
        g_ps[t] = s; g_pd[t] = d;
    }
    {   // v1 = W2^T a2_src, v2 = W2^T a2_dst, v3 = W2 column-mean
        float s1 = 0.f, s2 = 0.f, s3 = 0.f;
        for (int o = 0; o < 128; o++) {
            float w = W2[o * 256 + t];
            s1 += w * a2[o];
            s2 += w * a2[128 + o];
            s3 += w;
        }
        g_v1[t] = s1; g_v2[t] = s2; g_v3[t] = s3 * (1.f / 128.f);
    }
    if (t < 128) {
        int j = t >> 2, q = t & 3, k = q * 32 + j;
        g_b0p[t] = bih0[k] + bhh0[k];
        g_b1p[t] = bih1[k] + bhh1[k];
    }
    for (int idx = t; idx < 32 * 128; idx += 256) {
        int m = idx >> 7, r = idx & 127;
        int j = r >> 2, q = r & 3, k = q * 32 + j;
        g_WhhP0[idx] = Whh0[k * 32 + m];
        g_WihP1[idx] = Wih1[k * 32 + m];
        g_WhhP1[idx] = Whh1[k * 32 + m];
    }
    for (int idx = t; idx < NN * 128; idx += 256) {
        int n = idx >> 7, r = idx & 127;
        int j = r >> 2, q = r & 3, k = q * 32 + j;
        g_Wih0P[idx] = Wih0[k * NN + n];
    }
}

// ---------------- fused 2-layer GAT + lstm-layer-0 input transform ----------------
// One CTA per graph. Rank-2 collapse (h1 from two attention-weighted scalars)
// + exp-factorized leaky-softmax: exp(leaky(es_i+ed_j)) selects between
// exp(es_i)*exp(ed_j) and exp(.01 es_i)*exp(.01 ed_j) -> no MUFU in inner loops.
// Diagonal mask handled by post-subtraction.
__global__ void __launch_bounds__(256)
gat_kernel(const float* __restrict__ feat, const float* __restrict__ W1) {
    __shared__ float2 xsf[NN];                   // node features
    __shared__ float4 esp[4 * NN];               // (es, e^es, e^.01es, -)
    __shared__ float4 edp[4 * NN];               // (ed, e^ed, e^.01ed, -)
    __shared__ float4 wrec[256];                 // (wx, wy, v1, v2)
    __shared__ float  v3s[256];
    __shared__ float  wred[4 * NN * 3];          // [(j*4+h)*3]
    __shared__ float4 ap2[NN];                   // (es2, e^es2, e^.01es2, zb)
    __shared__ float4 dp2[NN];                   // (ed2, e^ed2, e^.01ed2, -)
    __shared__ float  pnum[4 * NN], pden[4 * NN];
    __shared__ float  exv[NN];
    __shared__ float  pX[256];
    __shared__ float  sps[8], spd[8];

    int g = blockIdx.x;
    int t = threadIdx.x;

    {   // stage folded weights + features
        float2 w = ((const float2*)W1)[t];
        wrec[t] = make_float4(w.x, w.y, g_v1[t], g_v2[t]);
        v3s[t] = g_v3[t];
    }
    if (t < NN) xsf[t] = ((const float2*)feat)[g * NN + t];
    if (t < 8)  { sps[t] = g_ps[t]; spd[t] = g_pd[t]; }
    __syncthreads();

    int h = t / NN, j = t - h * NN;              // valid for t < 204

    // phase A: es/ed + their exps (6 MUFU per thread, once)
    if (t < 4 * NN) {
        float2 x = xsf[j];
        float es = x.x * sps[h * 2] + x.y * sps[h * 2 + 1];
        float ed = x.x * spd[h * 2] + x.y * spd[h * 2 + 1];
        esp[t] = make_float4(es, __expf(es), __expf(0.01f * es), 0.f);
        edp[t] = make_float4(ed, __expf(ed), __expf(0.01f * ed), 0.f);
    }
    __syncthreads();

    float S0 = 0.f, S1 = 0.f;                    // live into phase C (same mapping)
    if (t < 4 * NN) {
        // phase B: softmax-weighted feature sums, MUFU-free inner loop
        float4 dp = edp[t];
        float negEd = -dp.x;
        float s = 0.f;
        int base = h * NN;
        #pragma unroll 3
        for (int i = 0; i < NN; i++) {
            float4 ap = esp[base + i];
            float2 x  = xsf[i];
            float w = (ap.x >= negEd) ? ap.y * dp.y : ap.z * dp.z;
            s  += w;
            S0 += w * x.x;
            S1 += w * x.y;
        }
        {   // remove diagonal term
            float4 aj = esp[t];
            float wj = (aj.x >= negEd) ? aj.y * dp.y : aj.z * dp.z;
            float2 xj = xsf[j];
            s  -= wj;
            S0 -= wj * xj.x;
            S1 -= wj * xj.y;
        }
        float si = 1.f / s;
        S0 *= si; S1 *= si;

        // phase C: reconstruct h1 elementwise (rank-2), elu, project v1/v2/v3
        float s1 = 0.f, s2 = 0.f, s3 = 0.f;
        int dbase = h * 64;
        #pragma unroll 8
        for (int dd = 0; dd < 64; dd++) {
            int d = dbase + dd;
            float4 wv = wrec[d];
            float hv = S0 * wv.x + S1 * wv.y;
            hv = (hv > 0.f) ? hv : (__expf(hv) - 1.f);
            s1 += hv * wv.z;
            s2 += hv * wv.w;
            s3 += hv * v3s[d];
        }
        float* wr = &wred[(j * 4 + h) * 3];
        wr[0] = s1; wr[1] = s2; wr[2] = s3;
    }
    __syncthreads();

    // combine head partials -> layer-2 logit ingredients + exps
    if (t < NN) {
        const float* wr = &wred[t * 12];
        float es2 = wr[0] + wr[3] + wr[6] + wr[9];
        float ed2 = wr[1] + wr[4] + wr[7] + wr[10];
        float zbv = wr[2] + wr[5] + wr[8] + wr[11];
        ap2[t] = make_float4(es2, __expf(es2), __expf(0.01f * es2), zbv);
        dp2[t] = make_float4(ed2, __expf(ed2), __expf(0.01f * ed2), 0.f);
    }
    __syncthreads();

    // phase D: layer-2 attention+mean, i-range split 4 ways over 204 threads
    if (t < 4 * NN) {
        int q = h;                                // reuse mapping: q*51 + j
        float4 dp = dp2[j];
        float negEd = -dp.x;
        float num = 0.f, den = 0.f;
        int i0 = q * 13, i1 = min(i0 + 13, NN);
        for (int i = i0; i < i1; i++) {
            float4 ap = ap2[i];
            float w = (ap.x >= negEd) ? ap.y * dp.y : ap.z * dp.z;
            num += w * ap.w;
            den += w;
        }
        pnum[q * NN + j] = num;
        pden[q * NN + j] = den;
    }
    __syncthreads();
    if (t < NN) {
        float4 dp = dp2[t];
        float4 aj = ap2[t];
        float wj = (aj.x >= -dp.x) ? aj.y * dp.y : aj.z * dp.z;
        float num = pnum[t] + pnum[NN + t] + pnum[2 * NN + t] + pnum[3 * NN + t]
                  - wj * aj.w;
        float den = pden[t] + pden[NN + t] + pden[2 * NN + t] + pden[3 * NN + t]
                  - wj;
        exv[t] = num / den;
    }
    __syncthreads();

    // phase E: lstm-layer-0 input gates, n-range split over 256 threads
    {
        int half = t >> 7, col = t & 127;
        int n0 = half ? 26 : 0, n1 = half ? NN : 26;
        float acc = 0.f;
        for (int n = n0; n < n1; n++) acc += exv[n] * g_Wih0P[n * 128 + col];
        pX[t] = acc;
    }
    __syncthreads();
    if (t < 128) g_X0g[g * 128 + t] = g_b0p[t] + pX[t] + pX[128 + t];
}

// exact-ish activations (same numerics class as the verified R4 run)
DINL float sigf(float x)    { return __fdividef(1.f, 1.f + __expf(-x)); }
DINL float tanhfast(float x){ return 1.f - __fdividef(2.f, __expf(2.f * x) + 1.f); }

// packed f32x2 helpers
DINL uint64_t pack2(float lo, float hi) {
    uint64_t r;
    asm("mov.b64 %0, {%1, %2};" : "=l"(r) : "f"(lo), "f"(hi));
    return r;
}
DINL uint64_t bcast2(float v) {
    uint64_t r;
    asm("mov.b64 %0, {%1, %1};" : "=l"(r) : "f"(v));
    return r;
}
DINL void unpack2(uint64_t p, float& lo, float& hi) {
    asm("mov.b64 {%0, %1}, %2;" : "=f"(lo), "=f"(hi) : "l"(p));
}
DINL void fma2(uint64_t& acc, uint64_t a, uint64_t b) {
    asm("fma.rn.f32x2 %0, %1, %2, %0;" : "+l"(acc) : "l"(a), "l"(b));
}
DINL uint64_t add2(uint64_t a, uint64_t b) {
    uint64_t r;
    asm("add.rn.f32x2 %0, %1, %2;" : "=l"(r) : "l"(a), "l"(b));
    return r;
}

// ---------------- 2-layer LSTM recurrence: one warp per batch element ----------------
// 1 warp/SMSP -> latency matters. Dependency chains split:
//   layer-0 gemv: two independent 16-deep half-chains (64 cyc vs 128)
//   layers 1+2:  merged loop, separate accumulators (128 cyc vs 256)
// fma.rn.f32x2 packed math throughout (bit-exact per-lane fma).
__global__ void __launch_bounds__(128)
lstm_kernel() {
    __shared__ ulonglong2 sW1[32 * 32], sW2[32 * 32];  // 32KB
    int tid = threadIdx.x;
    for (int idx = tid; idx < 32 * 32; idx += 128) {
        sW1[idx] = ((const ulonglong2*)g_WihP1)[idx];
        sW2[idx] = ((const ulonglong2*)g_WhhP1)[idx];
    }
    __syncthreads();
    int w = blockIdx.x * 4 + (tid >> 5);  // global warp = batch index f
    if (w >= FF) return;
    int lane = tid & 31;

    // layer-0 recurrent weights register-resident
    uint64_t rW0x[32], rW0y[32];
    #pragma unroll
    for (int m = 0; m < 32; m++) {
        ulonglong2 v = ((const ulonglong2*)g_WhhP0)[m * 32 + lane];
        rW0x[m] = v.x; rW0y[m] = v.y;
    }

    float4 b1 = ((const float4*)g_b1p)[lane];
    uint64_t b1xy = pack2(b1.x, b1.y), b1zw = pack2(b1.z, b1.w);
    float h0 = 0.f, c0 = 0.f, h1 = 0.f, c1 = 0.f;
    const float4* xgp = (const float4*)g_X0g;
    float4 xg = xgp[(0 * FF + w) * 32 + lane];    // prefetch t=0
    #pragma unroll 1
    for (int tt = 0; tt < BB; tt++) {
        float4 xgn = make_float4(0.f, 0.f, 0.f, 0.f);
        if (tt + 1 < BB) xgn = xgp[((tt + 1) * FF + w) * 32 + lane];  // hide L2 latency

        // layer-0 gemv: two independent half-chains
        uint64_t a01 = pack2(xg.x, xg.y), a23 = pack2(xg.z, xg.w);
        uint64_t p01 = 0, p23 = 0;                 // 0.0 bits == packed zeros
        #pragma unroll
        for (int m = 0; m < 16; m++) {
            uint64_t hmA = bcast2(__shfl_sync(0xffffffffu, h0, m));
            uint64_t hmB = bcast2(__shfl_sync(0xffffffffu, h0, m + 16));
            fma2(a01, hmA, rW0x[m]);
            fma2(a23, hmA, rW0y[m]);
            fma2(p01, hmB, rW0x[m + 16]);
            fma2(p23, hmB, rW0y[m + 16]);
        }
        a01 = add2(a01, p01); a23 = add2(a23, p23);
        float a0, a1, a2, a3;
        unpack2(a01, a0, a1); unpack2(a23, a2, a3);
        float gi = sigf(a0), gf = sigf(a1), gg = tanhfast(a2), go = sigf(a3);
        c0 = gf * c0 + gi * gg;
        h0 = go * tanhfast(c0);

        // layers 1+2 gemvs merged: independent accumulator pairs
        a01 = b1xy; a23 = b1zw;                    // sW1 gemv (input h0)
        p01 = 0; p23 = 0;                          // sW2 gemv (input h1)
        #pragma unroll
        for (int m = 0; m < 32; m++) {
            uint64_t hmA = bcast2(__shfl_sync(0xffffffffu, h0, m));
            uint64_t hmB = bcast2(__shfl_sync(0xffffffffu, h1, m));
            ulonglong2 wv1 = sW1[m * 32 + lane];
            ulonglong2 wv2 = sW2[m * 32 + lane];
            fma2(a01, hmA, wv1.x);
            fma2(a23, hmA, wv1.y);
            fma2(p01, hmB, wv2.x);
            fma2(p23, hmB, wv2.y);
        }
        a01 = add2(a01, p01); a23 = add2(a23, p23);
        unpack2(a01, a0, a1); unpack2(a23, a2, a3);
        gi = sigf(a0); gf = sigf(a1); gg = tanhfast(a2); go = sigf(a3);
        c1 = gf * c1 + gi * gg;
        h1 = go * tanhfast(c1);
        g_Y[(tt * FF + w) * 32 + lane] = h1;
        xg = xgn;
    }
}

// ---------------- final FC (float4 loads) ----------------
__global__ void fc_kernel(const float* __restrict__ Wfc, const float* __restrict__ bfc,
                          float* __restrict__ out) {
    int t = blockIdx.x;                 // time step (output row)
    int cls = threadIdx.x >> 5, lane = threadIdx.x & 31;
    const float4* y4 = (const float4*)(g_Y + t * 1600);
    const float4* w4 = (const float4*)(Wfc + cls * 1600);
    float acc = 0.f;
    for (int k = lane; k < 400; k += 32) {
        float4 a = y4[k], b = w4[k];
        acc += a.x * b.x + a.y * b.y + a.z * b.z + a.w * b.w;
    }
    #pragma unroll
    for (int off = 16; off; off >>= 1) acc += __shfl_xor_sync(0xffffffffu, acc, off);
    if (lane == 0) out[t * 8 + cls] = acc + bfc[cls];
}

extern "C" void kernel_launch(void* const* d_in, const int* in_sizes, int n_in,
                              void* d_out, int out_size) {
    const float* feat = (const float*)d_in[0];
    const float* W1   = (const float*)d_in[1];
    const float* a1   = (const float*)d_in[2];
    const float* W2   = (const float*)d_in[3];
    const float* a2   = (const float*)d_in[4];
    const float* Wih0 = (const float*)d_in[5];
    const float* Whh0 = (const float*)d_in[6];
    const float* bih0 = (const float*)d_in[7];
    const float* bhh0 = (const float*)d_in[8];
    const float* Wih1 = (const float*)d_in[9];
    const float* Whh1 = (const float*)d_in[10];
    const float* bih1 = (const float*)d_in[11];
    const float* bhh1 = (const float*)d_in[12];
    const float* Wfc  = (const float*)d_in[13];
    const float* bfc  = (const float*)d_in[14];
    float* out = (float*)d_out;

    prep_kernel<<<1, 256>>>(W1, a1, W2, a2, Wih0, Whh0, bih0, bhh0,
                            Wih1, Whh1, bih1, bhh1);
    gat_kernel<<<G, 256>>>(feat, W1);
    lstm_kernel<<<13, 128>>>();
    fc_kernel<<<BB, 256>>>(Wfc, bfc, out);
}